// round 11
// baseline (speedup 1.0000x reference)
#include <cuda_runtime.h>
#include <cuda_fp16.h>
#include <math.h>

#define N_NODES 50000
#define E_EDGES 800000
#define DIN     128
#define NH      4
#define ND      16
#define HD      64      // NH*ND
#define NEG_SLOPE 0.2f
#define CAP     128     // bucket capacity per node (P(deg>128) ~ 0)

#define MT 64
#define KP 64
#define PW 68
#define PROJ_BLOCKS  ((N_NODES + MT - 1) / MT)    // 782
#define EDGE_BLOCKS  ((E_EDGES + 255) / 256)      // 3125

typedef unsigned long long u64;

// ---------------- scratch (static device globals; no allocation) ----------------
// NOTE: device globals are zero-initialized at module load; g_cnt is re-zeroed
// by k_aggregate after each use, so the pipeline is self-cleaning with no init
// kernel.
__device__ __align__(16) __half g_feat_h[N_NODES * HD];  // projected features, fp16
__device__ __align__(16) float  g_el   [N_NODES * NH];
__device__ __align__(16) float  g_er   [N_NODES * NH];
__device__ int g_cnt  [N_NODES];          // dst histogram (zeroed by aggregate)
__device__ int g_esrc [N_NODES * CAP];    // fixed-capacity buckets of src ids

// ---------------- f32x2 packed-FMA helpers ----------------
__device__ __forceinline__ u64 pk2(float x, float y) {
    u64 r; asm("mov.b64 %0, {%1, %2};" : "=l"(r) : "f"(x), "f"(y)); return r;
}
__device__ __forceinline__ void upk2(u64 v, float& x, float& y) {
    asm("mov.b64 {%0, %1}, %2;" : "=f"(x), "=f"(y) : "l"(v));
}
__device__ __forceinline__ void ffma2(u64& c, u64 a, u64 b) {
    asm("fma.rn.f32x2 %0, %1, %2, %0;" : "+l"(c) : "l"(a), "l"(b));
}

// ---------------- pass 1 (fused): proj GEMM + direct bucket fill ----------------
__global__ __launch_bounds__(256) void k_proj_count(const float* __restrict__ h,
                                                    const float* __restrict__ W,
                                                    const float* __restrict__ attn_l,
                                                    const float* __restrict__ attn_r,
                                                    const int* __restrict__ src,
                                                    const int* __restrict__ dst) {
    __shared__ float w_s[KP * PW];
    __shared__ float h_s[MT * PW];

    if (blockIdx.x >= PROJ_BLOCKS) {
        // ---- bucket-fill part: light blocks hidden under GEMM blocks ----
        int e = (blockIdx.x - PROJ_BLOCKS) * 256 + threadIdx.x;
        if (e < E_EDGES) {
            int d = __ldg(dst + e);
            int pos = atomicAdd(&g_cnt[d], 1);
            if (pos < CAP)
                g_esrc[(d << 7) + pos] = __ldg(src + e);
        }
        return;
    }

    // ---- GEMM part ----
    const int tid = threadIdx.x;
    const int tc  = tid & 15;
    const int tn  = tid >> 4;
    const int nb  = blockIdx.x * MT;

    u64 acc2[4][2];
#pragma unroll
    for (int i = 0; i < 4; i++) { acc2[i][0] = 0ull; acc2[i][1] = 0ull; }

    for (int kb = 0; kb < DIN; kb += KP) {
        __syncthreads();
#pragma unroll
        for (int r = 0; r < 4; r++) {
            int idx = tid + r * 256;
            int kk = idx >> 4, c4 = (idx & 15) << 2;
            float4 v = *(const float4*)(W + (size_t)(kb + kk) * HD + c4);
            *(float4*)(w_s + kk * PW + c4) = v;
        }
#pragma unroll
        for (int r = 0; r < 4; r++) {
            int idx = tid + r * 256;
            int ln = idx >> 4, c4 = (idx & 15) << 2;
            float4 v = make_float4(0.f, 0.f, 0.f, 0.f);
            if (nb + ln < N_NODES)
                v = *(const float4*)(h + (size_t)(nb + ln) * DIN + kb + c4);
            *(float4*)(h_s + ln * PW + c4) = v;
        }
        __syncthreads();

#pragma unroll
        for (int kc = 0; kc < KP / 4; kc++) {
            const int k = kc * 4;
            float4 w0 = *(const float4*)(w_s + (k + 0) * PW + tc * 4);
            float4 w1 = *(const float4*)(w_s + (k + 1) * PW + tc * 4);
            float4 w2 = *(const float4*)(w_s + (k + 2) * PW + tc * 4);
            float4 w3 = *(const float4*)(w_s + (k + 3) * PW + tc * 4);
            u64 w0a = pk2(w0.x, w0.y), w0b = pk2(w0.z, w0.w);
            u64 w1a = pk2(w1.x, w1.y), w1b = pk2(w1.z, w1.w);
            u64 w2a = pk2(w2.x, w2.y), w2b = pk2(w2.z, w2.w);
            u64 w3a = pk2(w3.x, w3.y), w3b = pk2(w3.z, w3.w);
#pragma unroll
            for (int i = 0; i < 4; i++) {
                float4 hv = *(const float4*)(h_s + (tn * 4 + i) * PW + k);
                u64 hx = pk2(hv.x, hv.x);
                u64 hy = pk2(hv.y, hv.y);
                u64 hz = pk2(hv.z, hv.z);
                u64 hw = pk2(hv.w, hv.w);
                ffma2(acc2[i][0], hx, w0a); ffma2(acc2[i][1], hx, w0b);
                ffma2(acc2[i][0], hy, w1a); ffma2(acc2[i][1], hy, w1b);
                ffma2(acc2[i][0], hz, w2a); ffma2(acc2[i][1], hz, w2b);
                ffma2(acc2[i][0], hw, w3a); ffma2(acc2[i][1], hw, w3b);
            }
        }
    }

    const int head = tc >> 2;
    const int dbase = head * ND + (tc & 3) * 4;
    const float4 al = *(const float4*)(attn_l + dbase);
    const float4 ar = *(const float4*)(attn_r + dbase);

#pragma unroll
    for (int i = 0; i < 4; i++) {
        int node = nb + tn * 4 + i;
        if (node >= N_NODES) continue;
        float4 f;
        upk2(acc2[i][0], f.x, f.y);
        upk2(acc2[i][1], f.z, f.w);

        // store fp16 feat for the gather (el/er stay fp32, computed below)
        __half2 h0 = __floats2half2_rn(f.x, f.y);
        __half2 h1 = __floats2half2_rn(f.z, f.w);
        uint2 u;
        u.x = *(unsigned int*)&h0;
        u.y = *(unsigned int*)&h1;
        *(uint2*)(g_feat_h + (size_t)node * HD + tc * 4) = u;

        float pl = f.x * al.x + f.y * al.y + f.z * al.z + f.w * al.w;
        float pr = f.x * ar.x + f.y * ar.y + f.z * ar.z + f.w * ar.w;
        pl += __shfl_xor_sync(0xffffffffu, pl, 1);
        pl += __shfl_xor_sync(0xffffffffu, pl, 2);
        pr += __shfl_xor_sync(0xffffffffu, pr, 1);
        pr += __shfl_xor_sync(0xffffffffu, pr, 2);
        if ((tc & 3) == 0) {
            g_el[node * NH + head] = pl;
            g_er[node * NH + head] = pr;
        }
    }
}

// ---------------- pass 2: per-dst gather-aggregate (atomic-free, pipelined) ----------------
// One warp per dst node; resets g_cnt[d] to keep the pipeline self-cleaning.
__global__ __launch_bounds__(128) void k_aggregate(float* __restrict__ out) {
    int warp = (blockIdx.x * blockDim.x + threadIdx.x) >> 5;
    if (warp >= N_NODES) return;
    const int lane = threadIdx.x & 31;
    const int half = lane >> 4;
    const int j    = lane & 15;
    const int hh   = j >> 2;
    const int d    = warp;

    const float er_h = __ldg(&g_er[d * NH + hh]);
    const int beg = d << 7;                       // d * CAP
    int c = __ldg(&g_cnt[d]);
    if (lane == 0) g_cnt[d] = 0;                  // self-clean for next replay
    if (c > CAP) c = CAP;
    const int end = beg + c;

    float4 acc = make_float4(0.f, 0.f, 0.f, 0.f);
    float den = 0.0f;

    int k = beg + half;
    int s = (k < end) ? __ldg(&g_esrc[k]) : 0;
    for (; k < end; k += 2) {
        int sn = (k + 2 < end) ? __ldg(&g_esrc[k + 2]) : 0;   // prefetch
        float x = __ldg(&g_el[s * NH + hh]) + er_h;
        x = (x > 0.0f) ? x : NEG_SLOPE * x;
        float ex = __expf(x);
        uint2 u = __ldg((const uint2*)(g_feat_h + (size_t)s * HD + j * 4));
        __half2 h0 = *(__half2*)&u.x;
        __half2 h1 = *(__half2*)&u.y;
        float2 f01 = __half22float2(h0);
        float2 f23 = __half22float2(h1);
        den   += ex;
        acc.x += ex * f01.x;
        acc.y += ex * f01.y;
        acc.z += ex * f23.x;
        acc.w += ex * f23.y;
        s = sn;
    }

    acc.x += __shfl_xor_sync(0xffffffffu, acc.x, 16);
    acc.y += __shfl_xor_sync(0xffffffffu, acc.y, 16);
    acc.z += __shfl_xor_sync(0xffffffffu, acc.z, 16);
    acc.w += __shfl_xor_sync(0xffffffffu, acc.w, 16);
    den   += __shfl_xor_sync(0xffffffffu, den,   16);

    float r = (den > 0.0f) ? (1.0f / den) : 0.0f;
    acc.x *= r; acc.y *= r; acc.z *= r; acc.w *= r;

    acc.x += __shfl_xor_sync(0xffffffffu, acc.x, 4);
    acc.y += __shfl_xor_sync(0xffffffffu, acc.y, 4);
    acc.z += __shfl_xor_sync(0xffffffffu, acc.z, 4);
    acc.w += __shfl_xor_sync(0xffffffffu, acc.w, 4);
    acc.x += __shfl_xor_sync(0xffffffffu, acc.x, 8);
    acc.y += __shfl_xor_sync(0xffffffffu, acc.y, 8);
    acc.z += __shfl_xor_sync(0xffffffffu, acc.z, 8);
    acc.w += __shfl_xor_sync(0xffffffffu, acc.w, 8);

    if (lane < 4) {
        float4 o = make_float4(0.25f * acc.x, 0.25f * acc.y,
                               0.25f * acc.z, 0.25f * acc.w);
        *(float4*)(out + (size_t)d * ND + lane * 4) = o;
    }
}

// ---------------- launch ----------------
extern "C" void kernel_launch(void* const* d_in, const int* in_sizes, int n_in,
                              void* d_out, int out_size) {
    const float* h      = (const float*)d_in[0];
    const float* W      = (const float*)d_in[1];
    const float* attn_l = (const float*)d_in[2];
    const float* attn_r = (const float*)d_in[3];
    const int*   src    = (const int*)d_in[4];
    const int*   dst    = (const int*)d_in[5];
    float* out = (float*)d_out;

    k_proj_count<<<PROJ_BLOCKS + EDGE_BLOCKS, 256>>>(h, W, attn_l, attn_r, src, dst);
    k_aggregate <<<(N_NODES * 32 + 127) / 128, 128>>>(out);
}

// round 12
// speedup vs baseline: 1.9455x; 1.9455x over previous
#include <cuda_runtime.h>
#include <math.h>

#define N_NODES 50000
#define E_EDGES 800000
#define DIN     128
#define NH      4
#define ND      16
#define HD      64      // NH*ND
#define NEG_SLOPE 0.2f
#define CAP     128     // bucket capacity per node (P(deg>128) ~ 0)

#define MT 64
#define KP 64
#define PW 68
#define PROJ_BLOCKS  ((N_NODES + MT - 1) / MT)    // 782
#define EDGE_BLOCKS  ((E_EDGES + 255) / 256)      // 3125
#define AGG_BLOCKS   1184                         // 8 per SM
#define AGG_WARPS    (AGG_BLOCKS * 8)

typedef unsigned long long u64;

// ---------------- scratch (static device globals; no allocation) ----------------
// Device globals are zero-initialized at module load; g_cnt is re-zeroed by
// k_aggregate after each use, so the pipeline is self-cleaning with no init
// kernel.
__device__ __align__(16) float g_feat [N_NODES * HD];
__device__ __align__(16) float g_el   [N_NODES * NH];
__device__ __align__(16) float g_er   [N_NODES * NH];
__device__ int g_cnt  [N_NODES];          // dst histogram (zeroed by aggregate)
__device__ int g_esrc [N_NODES * CAP];    // fixed-capacity buckets of src ids

// ---------------- f32x2 packed-FMA helpers ----------------
__device__ __forceinline__ u64 pk2(float x, float y) {
    u64 r; asm("mov.b64 %0, {%1, %2};" : "=l"(r) : "f"(x), "f"(y)); return r;
}
__device__ __forceinline__ void upk2(u64 v, float& x, float& y) {
    asm("mov.b64 {%0, %1}, %2;" : "=f"(x), "=f"(y) : "l"(v));
}
__device__ __forceinline__ void ffma2(u64& c, u64 a, u64 b) {
    asm("fma.rn.f32x2 %0, %1, %2, %0;" : "+l"(c) : "l"(a), "l"(b));
}

// ---------------- pass 1 (fused): proj GEMM + direct bucket fill ----------------
__global__ __launch_bounds__(256) void k_proj_count(const float* __restrict__ h,
                                                    const float* __restrict__ W,
                                                    const float* __restrict__ attn_l,
                                                    const float* __restrict__ attn_r,
                                                    const int* __restrict__ src,
                                                    const int* __restrict__ dst) {
    __shared__ float w_s[KP * PW];
    __shared__ float h_s[MT * PW];

    if (blockIdx.x >= PROJ_BLOCKS) {
        // ---- bucket-fill part: light blocks hidden under GEMM blocks ----
        int e = (blockIdx.x - PROJ_BLOCKS) * 256 + threadIdx.x;
        if (e < E_EDGES) {
            int d = __ldg(dst + e);
            int pos = atomicAdd(&g_cnt[d], 1);
            if (pos < CAP)
                g_esrc[(d << 7) + pos] = __ldg(src + e);
        }
        return;
    }

    // ---- GEMM part ----
    const int tid = threadIdx.x;
    const int tc  = tid & 15;
    const int tn  = tid >> 4;
    const int nb  = blockIdx.x * MT;

    u64 acc2[4][2];
#pragma unroll
    for (int i = 0; i < 4; i++) { acc2[i][0] = 0ull; acc2[i][1] = 0ull; }

    for (int kb = 0; kb < DIN; kb += KP) {
        __syncthreads();
#pragma unroll
        for (int r = 0; r < 4; r++) {
            int idx = tid + r * 256;
            int kk = idx >> 4, c4 = (idx & 15) << 2;
            float4 v = *(const float4*)(W + (size_t)(kb + kk) * HD + c4);
            *(float4*)(w_s + kk * PW + c4) = v;
        }
#pragma unroll
        for (int r = 0; r < 4; r++) {
            int idx = tid + r * 256;
            int ln = idx >> 4, c4 = (idx & 15) << 2;
            float4 v = make_float4(0.f, 0.f, 0.f, 0.f);
            if (nb + ln < N_NODES)
                v = *(const float4*)(h + (size_t)(nb + ln) * DIN + kb + c4);
            *(float4*)(h_s + ln * PW + c4) = v;
        }
        __syncthreads();

#pragma unroll
        for (int kc = 0; kc < KP / 4; kc++) {
            const int k = kc * 4;
            float4 w0 = *(const float4*)(w_s + (k + 0) * PW + tc * 4);
            float4 w1 = *(const float4*)(w_s + (k + 1) * PW + tc * 4);
            float4 w2 = *(const float4*)(w_s + (k + 2) * PW + tc * 4);
            float4 w3 = *(const float4*)(w_s + (k + 3) * PW + tc * 4);
            u64 w0a = pk2(w0.x, w0.y), w0b = pk2(w0.z, w0.w);
            u64 w1a = pk2(w1.x, w1.y), w1b = pk2(w1.z, w1.w);
            u64 w2a = pk2(w2.x, w2.y), w2b = pk2(w2.z, w2.w);
            u64 w3a = pk2(w3.x, w3.y), w3b = pk2(w3.z, w3.w);
#pragma unroll
            for (int i = 0; i < 4; i++) {
                float4 hv = *(const float4*)(h_s + (tn * 4 + i) * PW + k);
                u64 hx = pk2(hv.x, hv.x);
                u64 hy = pk2(hv.y, hv.y);
                u64 hz = pk2(hv.z, hv.z);
                u64 hw = pk2(hv.w, hv.w);
                ffma2(acc2[i][0], hx, w0a); ffma2(acc2[i][1], hx, w0b);
                ffma2(acc2[i][0], hy, w1a); ffma2(acc2[i][1], hy, w1b);
                ffma2(acc2[i][0], hz, w2a); ffma2(acc2[i][1], hz, w2b);
                ffma2(acc2[i][0], hw, w3a); ffma2(acc2[i][1], hw, w3b);
            }
        }
    }

    const int head = tc >> 2;
    const int dbase = head * ND + (tc & 3) * 4;
    const float4 al = *(const float4*)(attn_l + dbase);
    const float4 ar = *(const float4*)(attn_r + dbase);

#pragma unroll
    for (int i = 0; i < 4; i++) {
        int node = nb + tn * 4 + i;
        if (node >= N_NODES) continue;
        float4 f;
        upk2(acc2[i][0], f.x, f.y);
        upk2(acc2[i][1], f.z, f.w);
        *(float4*)(g_feat + (size_t)node * HD + tc * 4) = f;

        float pl = f.x * al.x + f.y * al.y + f.z * al.z + f.w * al.w;
        float pr = f.x * ar.x + f.y * ar.y + f.z * ar.z + f.w * ar.w;
        pl += __shfl_xor_sync(0xffffffffu, pl, 1);
        pl += __shfl_xor_sync(0xffffffffu, pl, 2);
        pr += __shfl_xor_sync(0xffffffffu, pr, 1);
        pr += __shfl_xor_sync(0xffffffffu, pr, 2);
        if ((tc & 3) == 0) {
            g_el[node * NH + head] = pl;
            g_er[node * NH + head] = pr;
        }
    }
}

// ---------------- pass 2: persistent per-dst gather-aggregate ----------------
// Persistent warps grid-stride over destination nodes (removes wave
// quantization of 12500 tiny blocks and averages degree variance).
// Each warp: half = lane>>4 picks one of 2 edges/iter; j = lane&15 covers
// (head hh=j>>2, dims 4*(j&3)..+3). Resets g_cnt[d] for self-cleaning.
__global__ __launch_bounds__(256) void k_aggregate(float* __restrict__ out) {
    const int lane = threadIdx.x & 31;
    const int gw   = (blockIdx.x * 256 + threadIdx.x) >> 5;
    const int half = lane >> 4;
    const int j    = lane & 15;
    const int hh   = j >> 2;

    for (int d = gw; d < N_NODES; d += AGG_WARPS) {
        const float er_h = __ldg(&g_er[d * NH + hh]);
        const int beg = d << 7;                   // d * CAP
        int c = __ldg(&g_cnt[d]);
        if (lane == 0) g_cnt[d] = 0;              // self-clean for next replay
        if (c > CAP) c = CAP;
        const int end = beg + c;

        float4 acc = make_float4(0.f, 0.f, 0.f, 0.f);
        float den = 0.0f;

        int k = beg + half;
        int s = (k < end) ? __ldg(&g_esrc[k]) : 0;
        for (; k < end; k += 2) {
            int sn = (k + 2 < end) ? __ldg(&g_esrc[k + 2]) : 0;   // prefetch
            float x = __ldg(&g_el[s * NH + hh]) + er_h;
            x = (x > 0.0f) ? x : NEG_SLOPE * x;
            float ex = __expf(x);
            float4 f = __ldg((const float4*)(&g_feat[(size_t)s * HD + j * 4]));
            den   += ex;
            acc.x += ex * f.x;
            acc.y += ex * f.y;
            acc.z += ex * f.z;
            acc.w += ex * f.w;
            s = sn;
        }

        acc.x += __shfl_xor_sync(0xffffffffu, acc.x, 16);
        acc.y += __shfl_xor_sync(0xffffffffu, acc.y, 16);
        acc.z += __shfl_xor_sync(0xffffffffu, acc.z, 16);
        acc.w += __shfl_xor_sync(0xffffffffu, acc.w, 16);
        den   += __shfl_xor_sync(0xffffffffu, den,   16);

        float r = (den > 0.0f) ? (1.0f / den) : 0.0f;
        acc.x *= r; acc.y *= r; acc.z *= r; acc.w *= r;

        acc.x += __shfl_xor_sync(0xffffffffu, acc.x, 4);
        acc.y += __shfl_xor_sync(0xffffffffu, acc.y, 4);
        acc.z += __shfl_xor_sync(0xffffffffu, acc.z, 4);
        acc.w += __shfl_xor_sync(0xffffffffu, acc.w, 4);
        acc.x += __shfl_xor_sync(0xffffffffu, acc.x, 8);
        acc.y += __shfl_xor_sync(0xffffffffu, acc.y, 8);
        acc.z += __shfl_xor_sync(0xffffffffu, acc.z, 8);
        acc.w += __shfl_xor_sync(0xffffffffu, acc.w, 8);

        if (lane < 4) {
            float4 o = make_float4(0.25f * acc.x, 0.25f * acc.y,
                                   0.25f * acc.z, 0.25f * acc.w);
            *(float4*)(out + (size_t)d * ND + lane * 4) = o;
        }
    }
}

// ---------------- launch ----------------
extern "C" void kernel_launch(void* const* d_in, const int* in_sizes, int n_in,
                              void* d_out, int out_size) {
    const float* h      = (const float*)d_in[0];
    const float* W      = (const float*)d_in[1];
    const float* attn_l = (const float*)d_in[2];
    const float* attn_r = (const float*)d_in[3];
    const int*   src    = (const int*)d_in[4];
    const int*   dst    = (const int*)d_in[5];
    float* out = (float*)d_out;

    k_proj_count<<<PROJ_BLOCKS + EDGE_BLOCKS, 256>>>(h, W, attn_l, attn_r, src, dst);
    k_aggregate <<<AGG_BLOCKS, 256>>>(out);
}

// round 17
// speedup vs baseline: 2.5089x; 1.2896x over previous
#include <cuda_runtime.h>
#include <math.h>

#define N_NODES 50000
#define E_EDGES 800000
#define DIN     128
#define NH      4
#define ND      16
#define HD      64      // NH*ND
#define NEG_SLOPE 0.2f
#define CAP     128     // bucket capacity per node (P(deg>128) ~ 0)

#define MT 128              // nodes per block
#define KP 64               // k-phase width
#define PW 64               // smem row pitch (floats) — no padding needed:
                            // w reads are 64-float contiguous, h reads broadcast
#define PROJ_BLOCKS  ((N_NODES + MT - 1) / MT)    // 391
#define EDGE_BLOCKS  ((E_EDGES + 255) / 256)      // 3125

typedef unsigned long long u64;

// ---------------- scratch (static device globals; no allocation) ----------------
// Device globals are zero-initialized at module load; g_cnt is re-zeroed by
// k_aggregate after each use, so the pipeline is self-cleaning (no init kernel).
__device__ __align__(16) float g_feat [N_NODES * HD];
__device__ __align__(16) float g_el   [N_NODES * NH];
__device__ __align__(16) float g_er   [N_NODES * NH];
__device__ int g_cnt  [N_NODES];          // dst histogram (zeroed by aggregate)
__device__ int g_esrc [N_NODES * CAP];    // fixed-capacity buckets of src ids

// ---------------- f32x2 packed-FMA helpers ----------------
__device__ __forceinline__ u64 pk2(float x, float y) {
    u64 r; asm("mov.b64 %0, {%1, %2};" : "=l"(r) : "f"(x), "f"(y)); return r;
}
__device__ __forceinline__ void upk2(u64 v, float& x, float& y) {
    asm("mov.b64 {%0, %1}, %2;" : "=f"(x), "=f"(y) : "l"(v));
}
__device__ __forceinline__ void ffma2(u64& c, u64 a, u64 b) {
    asm("fma.rn.f32x2 %0, %1, %2, %0;" : "+l"(c) : "l"(a), "l"(b));
}

// ---------------- pass 1 (fused): proj GEMM (8x4 micro-tile) + bucket fill ----------------
__global__ __launch_bounds__(256) void k_proj_count(const float* __restrict__ h,
                                                    const float* __restrict__ W,
                                                    const float* __restrict__ attn_l,
                                                    const float* __restrict__ attn_r,
                                                    const int* __restrict__ src,
                                                    const int* __restrict__ dst) {
    __shared__ float w_s[KP * PW];     // 16 KB
    __shared__ float h_s[MT * PW];     // 32 KB

    if (blockIdx.x >= PROJ_BLOCKS) {
        // ---- bucket-fill part: light blocks overlapped with GEMM blocks ----
        int e = (blockIdx.x - PROJ_BLOCKS) * 256 + threadIdx.x;
        if (e < E_EDGES) {
            int d = __ldg(dst + e);
            int pos = atomicAdd(&g_cnt[d], 1);
            if (pos < CAP)
                g_esrc[(d << 7) + pos] = __ldg(src + e);
        }
        return;
    }

    // ---- GEMM part: 128-node tile, each thread 8 nodes x 4 cols ----
    const int tid = threadIdx.x;
    const int tc  = tid & 15;          // col-group: cols 4*tc .. 4*tc+3
    const int tn  = tid >> 4;          // node-group: rows 8*tn .. 8*tn+7
    const int nb  = blockIdx.x * MT;

    u64 acc2[8][2];
#pragma unroll
    for (int i = 0; i < 8; i++) { acc2[i][0] = 0ull; acc2[i][1] = 0ull; }

    for (int kb = 0; kb < DIN; kb += KP) {
        __syncthreads();
        // load W[kb..kb+63][0..63]  (1024 float4, 4 per thread)
#pragma unroll
        for (int r = 0; r < 4; r++) {
            int idx = tid + r * 256;           // float4 index
            int kk = idx >> 4, c4 = (idx & 15) << 2;
            float4 v = *(const float4*)(W + (size_t)(kb + kk) * HD + c4);
            *(float4*)(w_s + kk * PW + c4) = v;
        }
        // load h[nb..nb+127][kb..kb+63]  (2048 float4, 8 per thread)
#pragma unroll
        for (int r = 0; r < 8; r++) {
            int idx = tid + r * 256;
            int ln = idx >> 4, c4 = (idx & 15) << 2;
            float4 v = make_float4(0.f, 0.f, 0.f, 0.f);
            if (nb + ln < N_NODES)
                v = *(const float4*)(h + (size_t)(nb + ln) * DIN + kb + c4);
            *(float4*)(h_s + ln * PW + c4) = v;
        }
        __syncthreads();

#pragma unroll
        for (int kc = 0; kc < KP / 4; kc++) {
            const int k = kc * 4;
            float4 w0 = *(const float4*)(w_s + (k + 0) * PW + tc * 4);
            float4 w1 = *(const float4*)(w_s + (k + 1) * PW + tc * 4);
            float4 w2 = *(const float4*)(w_s + (k + 2) * PW + tc * 4);
            float4 w3 = *(const float4*)(w_s + (k + 3) * PW + tc * 4);
            u64 w0a = pk2(w0.x, w0.y), w0b = pk2(w0.z, w0.w);
            u64 w1a = pk2(w1.x, w1.y), w1b = pk2(w1.z, w1.w);
            u64 w2a = pk2(w2.x, w2.y), w2b = pk2(w2.z, w2.w);
            u64 w3a = pk2(w3.x, w3.y), w3b = pk2(w3.z, w3.w);
#pragma unroll
            for (int i = 0; i < 8; i++) {
                float4 hv = *(const float4*)(h_s + (tn * 8 + i) * PW + k);
                u64 hx = pk2(hv.x, hv.x);
                u64 hy = pk2(hv.y, hv.y);
                u64 hz = pk2(hv.z, hv.z);
                u64 hw = pk2(hv.w, hv.w);
                ffma2(acc2[i][0], hx, w0a); ffma2(acc2[i][1], hx, w0b);
                ffma2(acc2[i][0], hy, w1a); ffma2(acc2[i][1], hy, w1b);
                ffma2(acc2[i][0], hz, w2a); ffma2(acc2[i][1], hz, w2b);
                ffma2(acc2[i][0], hw, w3a); ffma2(acc2[i][1], hw, w3b);
            }
        }
    }

    // epilogue: store feat, compute el/er
    const int head = tc >> 2;
    const int dbase = head * ND + (tc & 3) * 4;
    const float4 al = *(const float4*)(attn_l + dbase);
    const float4 ar = *(const float4*)(attn_r + dbase);

#pragma unroll
    for (int i = 0; i < 8; i++) {
        int node = nb + tn * 8 + i;
        if (node >= N_NODES) continue;
        float4 f;
        upk2(acc2[i][0], f.x, f.y);
        upk2(acc2[i][1], f.z, f.w);
        *(float4*)(g_feat + (size_t)node * HD + tc * 4) = f;

        float pl = f.x * al.x + f.y * al.y + f.z * al.z + f.w * al.w;
        float pr = f.x * ar.x + f.y * ar.y + f.z * ar.z + f.w * ar.w;
        // reduce across the 4 consecutive lanes covering this head
        pl += __shfl_xor_sync(0xffffffffu, pl, 1);
        pl += __shfl_xor_sync(0xffffffffu, pl, 2);
        pr += __shfl_xor_sync(0xffffffffu, pr, 1);
        pr += __shfl_xor_sync(0xffffffffu, pr, 2);
        if ((tc & 3) == 0) {
            g_el[node * NH + head] = pl;
            g_er[node * NH + head] = pr;
        }
    }
}

// ---------------- pass 2: per-dst gather-aggregate (one warp per node) ----------------
// 12500 small blocks, warp d adjacent to warp d+1 — cross-warp spatial locality
// on g_esrc / g_er / out. Resets g_cnt[d] for self-cleaning replay.
__global__ __launch_bounds__(128) void k_aggregate(float* __restrict__ out) {
    int warp = (blockIdx.x * blockDim.x + threadIdx.x) >> 5;
    if (warp >= N_NODES) return;
    const int lane = threadIdx.x & 31;
    const int half = lane >> 4;
    const int j    = lane & 15;
    const int hh   = j >> 2;
    const int d    = warp;

    const float er_h = __ldg(&g_er[d * NH + hh]);
    const int beg = d << 7;                       // d * CAP
    int c = __ldg(&g_cnt[d]);
    if (lane == 0) g_cnt[d] = 0;                  // self-clean for next replay
    if (c > CAP) c = CAP;
    const int end = beg + c;

    float4 acc = make_float4(0.f, 0.f, 0.f, 0.f);
    float den = 0.0f;

    int k = beg + half;
    int s = (k < end) ? __ldg(&g_esrc[k]) : 0;
    for (; k < end; k += 2) {
        int sn = (k + 2 < end) ? __ldg(&g_esrc[k + 2]) : 0;   // prefetch
        float x = __ldg(&g_el[s * NH + hh]) + er_h;
        x = (x > 0.0f) ? x : NEG_SLOPE * x;
        float ex = __expf(x);
        float4 f = __ldg((const float4*)(&g_feat[(size_t)s * HD + j * 4]));
        den   += ex;
        acc.x += ex * f.x;
        acc.y += ex * f.y;
        acc.z += ex * f.z;
        acc.w += ex * f.w;
        s = sn;
    }

    acc.x += __shfl_xor_sync(0xffffffffu, acc.x, 16);
    acc.y += __shfl_xor_sync(0xffffffffu, acc.y, 16);
    acc.z += __shfl_xor_sync(0xffffffffu, acc.z, 16);
    acc.w += __shfl_xor_sync(0xffffffffu, acc.w, 16);
    den   += __shfl_xor_sync(0xffffffffu, den,   16);

    float r = (den > 0.0f) ? (1.0f / den) : 0.0f;
    acc.x *= r; acc.y *= r; acc.z *= r; acc.w *= r;

    acc.x += __shfl_xor_sync(0xffffffffu, acc.x, 4);
    acc.y += __shfl_xor_sync(0xffffffffu, acc.y, 4);
    acc.z += __shfl_xor_sync(0xffffffffu, acc.z, 4);
    acc.w += __shfl_xor_sync(0xffffffffu, acc.w, 4);
    acc.x += __shfl_xor_sync(0xffffffffu, acc.x, 8);
    acc.y += __shfl_xor_sync(0xffffffffu, acc.y, 8);
    acc.z += __shfl_xor_sync(0xffffffffu, acc.z, 8);
    acc.w += __shfl_xor_sync(0xffffffffu, acc.w, 8);

    if (lane < 4) {
        float4 o = make_float4(0.25f * acc.x, 0.25f * acc.y,
                               0.25f * acc.z, 0.25f * acc.w);
        *(float4*)(out + (size_t)d * ND + lane * 4) = o;
    }
}

// ---------------- launch ----------------
extern "C" void kernel_launch(void* const* d_in, const int* in_sizes, int n_in,
                              void* d_out, int out_size) {
    const float* h      = (const float*)d_in[0];
    const float* W      = (const float*)d_in[1];
    const float* attn_l = (const float*)d_in[2];
    const float* attn_r = (const float*)d_in[3];
    const int*   src    = (const int*)d_in[4];
    const int*   dst    = (const int*)d_in[5];
    float* out = (float*)d_out;

    k_proj_count<<<PROJ_BLOCKS + EDGE_BLOCKS, 256>>>(h, W, attn_l, attn_r, src, dst);
    k_aggregate <<<(N_NODES * 32 + 127) / 128, 128>>>(out);
}